// round 13
// baseline (speedup 1.0000x reference)
#include <cuda_runtime.h>
#include <cuda_bf16.h>
#include <cstdint>

// Problem dims
static constexpr int MROWS = 8192;   // B*S
static constexpr int DIN   = 4096;
static constexpr int DOUT  = 4096;

// GEMM tiling (2 CTAs/SM)
static constexpr int BM = 128, BN = 128, BK = 64;
static constexpr int KTILES = DIN / BK;          // 64
static constexpr int TILE_BYTES  = BM * BK * 2;  // 16384 per operand
static constexpr int STAGE_BYTES = 2 * TILE_BYTES;
static constexpr int SMEM_TOTAL  = 3 * STAGE_BYTES;  // 98304

// Quantized operands (device globals: no cudaMalloc allowed)
__device__ __nv_bfloat16 g_xq[(size_t)MROWS * DIN];  // 64 MB
__device__ __nv_bfloat16 g_wq[(size_t)DOUT * DIN];   // 32 MB

// ---------- helpers (base-sm_103-safe PTX only) ----------
__device__ __forceinline__ uint32_t smem_u32(const void* p) {
    uint32_t a;
    asm("{ .reg .u64 t; cvta.to.shared.u64 t, %1; cvt.u32.u64 %0, t; }"
        : "=r"(a) : "l"(p));
    return a;
}
__device__ __forceinline__ uint32_t swz(uint32_t o) { return o ^ ((o >> 3) & 0x70); }

__device__ __forceinline__ void cpasync16(uint32_t s, const void* g) {
    asm volatile("cp.async.cg.shared.global [%0], [%1], 16;" :: "r"(s), "l"(g));
}
__device__ __forceinline__ void cp_commit() {
    asm volatile("cp.async.commit_group;" ::: "memory");
}
__device__ __forceinline__ void cp_wait1() {
    asm volatile("cp.async.wait_group 1;" ::: "memory");
}
__device__ __forceinline__ void ldmx4(uint32_t* r, uint32_t addr) {
    asm volatile("ldmatrix.sync.aligned.m8n8.x4.shared.b16 {%0,%1,%2,%3}, [%4];"
                 : "=r"(r[0]), "=r"(r[1]), "=r"(r[2]), "=r"(r[3]) : "r"(addr));
}
__device__ __forceinline__ void mma16816(float* d, const uint32_t* a, const uint32_t* b) {
    asm volatile(
        "mma.sync.aligned.m16n8k16.row.col.f32.bf16.bf16.f32 "
        "{%0,%1,%2,%3}, {%4,%5,%6,%7}, {%8,%9}, {%0,%1,%2,%3};"
        : "+f"(d[0]), "+f"(d[1]), "+f"(d[2]), "+f"(d[3])
        : "r"(a[0]), "r"(a[1]), "r"(a[2]), "r"(a[3]), "r"(b[0]), "r"(b[1]));
}

// ---------- fused quantization (block-level dispatch, 8 elems/thread) ----------
static constexpr size_t NX = (size_t)MROWS * DIN;   // 33.55M
static constexpr size_t NW = (size_t)DOUT * DIN;    // 16.78M
static constexpr int ELEMS_PER_BLK = 256 * 8;       // 2048
static constexpr unsigned NXB = (unsigned)(NX / ELEMS_PER_BLK);  // 16384
static constexpr unsigned NWB = (unsigned)(NW / ELEMS_PER_BLK);  // 8192

__global__ void __launch_bounds__(256) quant_kernel(
    const float* __restrict__ x, const float* __restrict__ w,
    const float* __restrict__ wscale, const float* __restrict__ iscale) {
    const unsigned b = blockIdx.x;
    if (b < NXB) {
        const size_t i = (size_t)b * ELEMS_PER_BLK + (size_t)threadIdx.x * 8;
        const float is = iscale[0];
        float4 v0 = *reinterpret_cast<const float4*>(x + i);
        float4 v1 = *reinterpret_cast<const float4*>(x + i + 4);
        __nv_bfloat162 p0 = __floats2bfloat162_rn(truncf(v0.x * is), truncf(v0.y * is));
        __nv_bfloat162 p1 = __floats2bfloat162_rn(truncf(v0.z * is), truncf(v0.w * is));
        __nv_bfloat162 p2 = __floats2bfloat162_rn(truncf(v1.x * is), truncf(v1.y * is));
        __nv_bfloat162 p3 = __floats2bfloat162_rn(truncf(v1.z * is), truncf(v1.w * is));
        uint4 u;
        u.x = *reinterpret_cast<uint32_t*>(&p0);
        u.y = *reinterpret_cast<uint32_t*>(&p1);
        u.z = *reinterpret_cast<uint32_t*>(&p2);
        u.w = *reinterpret_cast<uint32_t*>(&p3);
        *reinterpret_cast<uint4*>(g_xq + i) = u;
    } else {
        const size_t i = (size_t)(b - NXB) * ELEMS_PER_BLK + (size_t)threadIdx.x * 8;
        const int row = (int)(i >> 12);  // / DIN (8 elems never cross a row)
        const float ws = wscale[row];
        float4 v0 = *reinterpret_cast<const float4*>(w + i);
        float4 v1 = *reinterpret_cast<const float4*>(w + i + 4);
        float f0 = (float)(int8_t)__float2int_rn(v0.x * ws);
        float f1 = (float)(int8_t)__float2int_rn(v0.y * ws);
        float f2 = (float)(int8_t)__float2int_rn(v0.z * ws);
        float f3 = (float)(int8_t)__float2int_rn(v0.w * ws);
        float f4 = (float)(int8_t)__float2int_rn(v1.x * ws);
        float f5 = (float)(int8_t)__float2int_rn(v1.y * ws);
        float f6 = (float)(int8_t)__float2int_rn(v1.z * ws);
        float f7 = (float)(int8_t)__float2int_rn(v1.w * ws);
        __nv_bfloat162 p0 = __floats2bfloat162_rn(f0, f1);
        __nv_bfloat162 p1 = __floats2bfloat162_rn(f2, f3);
        __nv_bfloat162 p2 = __floats2bfloat162_rn(f4, f5);
        __nv_bfloat162 p3 = __floats2bfloat162_rn(f6, f7);
        uint4 u;
        u.x = *reinterpret_cast<uint32_t*>(&p0);
        u.y = *reinterpret_cast<uint32_t*>(&p1);
        u.z = *reinterpret_cast<uint32_t*>(&p2);
        u.w = *reinterpret_cast<uint32_t*>(&p3);
        *reinterpret_cast<uint4*>(g_wq + i) = u;
    }
}

// ---------- GEMM: out = (Xq @ Wq^T) * sc + bias * sc ----------
// R12 winner, plus a one-time phase skew for the second occupancy slot so the
// two co-resident CTAs' k-tile boundaries stop hitting the barrier in lockstep.
__global__ void __launch_bounds__(256, 2) gemm_kernel(
    const float* __restrict__ bias, const float* __restrict__ wscale,
    const float* __restrict__ iscale, float* __restrict__ out) {
    extern __shared__ char smem[];
    const uint32_t sbase = smem_u32(smem);
    const int tid  = threadIdx.x;
    const int lane = tid & 31;
    const int warp = tid >> 5;
    const int wm = (warp >> 2) * 64;
    const int wn = (warp & 3) * 32;
    const int m0 = blockIdx.y * BM;
    const int n0 = blockIdx.x * BN;

    const int lrow0 = tid >> 3;
    const int lcol  = (tid & 7) * 8;
    const __nv_bfloat16* abase = g_xq + (size_t)(m0 + lrow0) * DIN + lcol;
    const __nv_bfloat16* bbase = g_wq + (size_t)(n0 + lrow0) * DIN + lcol;
    uint32_t soff[4];
#pragma unroll
    for (int u = 0; u < 4; u++)
        soff[u] = swz((uint32_t)((lrow0 + u * 32) * 128 + lcol * 2));

    auto load_tile = [&](int kt, uint32_t sA) {
        const uint32_t sB = sA + TILE_BYTES;
        const __nv_bfloat16* a0 = abase + (size_t)kt * BK;
        const __nv_bfloat16* b0 = bbase + (size_t)kt * BK;
#pragma unroll
        for (int u = 0; u < 4; u++) {
            cpasync16(sA + soff[u], a0 + (size_t)u * 32 * DIN);
            cpasync16(sB + soff[u], b0 + (size_t)u * 32 * DIN);
        }
    };

    float acc[4][4][4];
#pragma unroll
    for (int a = 0; a < 4; a++)
#pragma unroll
        for (int b = 0; b < 4; b++)
#pragma unroll
            for (int c = 0; c < 4; c++) acc[a][b][c] = 0.f;

    const int g = lane >> 3, r = lane & 7;
    uint32_t arow[4], brow[2];
#pragma unroll
    for (int mi = 0; mi < 4; mi++)
        arow[mi] = (uint32_t)((wm + mi * 16 + r + ((g & 1) ? 8 : 0)) * 128 +
                              (((g & 2) ? 8 : 0) * 2));
#pragma unroll
    for (int nb = 0; nb < 2; nb++)
        brow[nb] = (uint32_t)((wn + nb * 16 + r + ((g & 2) ? 8 : 0)) * 128 +
                              (((g & 1) ? 8 : 0) * 2));

    uint32_t bf[2][4][2];
    uint32_t af[2][4];

    auto loadB = [&](uint32_t sB, uint32_t kbo, uint32_t (*dst)[2]) {
#pragma unroll
        for (int nb = 0; nb < 2; nb++) {
            uint32_t t[4];
            ldmx4(t, sB + swz(brow[nb] + kbo));
            dst[nb * 2 + 0][0] = t[0]; dst[nb * 2 + 0][1] = t[1];
            dst[nb * 2 + 1][0] = t[2]; dst[nb * 2 + 1][1] = t[3];
        }
    };

    // prologue: stages 0,1 in flight; tile0 resident; frags(kt0,ks0) loaded
    load_tile(0, sbase); cp_commit();
    load_tile(1, sbase + STAGE_BYTES); cp_commit();

    // One-time phase skew (~half a k-iteration) for the second occupancy slot.
    // Wave = 148 SMs x 2 slots = 296 CTAs; slot 1 is bids [148,296) mod 296.
    {
        const unsigned bid = blockIdx.y * gridDim.x + blockIdx.x;
        if ((bid % 296u) >= 148u) __nanosleep(600);
    }

    cp_wait1();
    __syncthreads();
    loadB(sbase + TILE_BYTES, 0, bf[0]);
    ldmx4(af[0], sbase + swz(arow[0]));

    const uint32_t slast = sbase + 2 * STAGE_BYTES;
    uint32_t cs = sbase;
    uint32_t ls = slast;

    for (int kt = 0; kt < KTILES; kt++) {
        if (kt + 2 < KTILES) load_tile(kt + 2, ls);
        cp_commit();

        const uint32_t sA = cs, sB = cs + TILE_BYTES;
        const uint32_t ns = (cs == slast) ? sbase : cs + STAGE_BYTES;
#pragma unroll
        for (int ks = 0; ks < 4; ks++) {
            if (ks == 3) cp_wait1();  // drain overlaps final ks block's MMAs
            const uint32_t kbo = (uint32_t)(ks * 32);
            const int cur = ks & 1;
#pragma unroll
            for (int mi = 0; mi < 4; mi++) {
                if (mi < 3) {
                    ldmx4(af[(mi + 1) & 1], sA + swz(arow[mi + 1] + kbo));
                } else if (ks < 3) {
                    loadB(sB, kbo + 32, bf[cur ^ 1]);
                    ldmx4(af[0], sA + swz(arow[0] + kbo + 32));
                }
#pragma unroll
                for (int ni = 0; ni < 4; ni++)
                    mma16816(acc[mi][ni], af[mi & 1], bf[cur][ni]);
            }
        }
        __syncthreads();
        if (kt + 1 < KTILES) {
            loadB(ns + TILE_BYTES, 0, bf[0]);
            ldmx4(af[0], ns + swz(arow[0]));
        }
        ls = cs;
        cs = ns;
    }

    // epilogue
    const float is = iscale[0];
    float sc[4][2], bq[4][2];
#pragma unroll
    for (int ni = 0; ni < 4; ni++)
#pragma unroll
        for (int j = 0; j < 2; j++) {
            const int n = n0 + wn + ni * 8 + (lane & 3) * 2 + j;
            const float s = 1.0f / (wscale[n] * is);
            sc[ni][j] = s;
            bq[ni][j] = bias[n] * s;
        }
    const int mrow = m0 + wm + (lane >> 2);
    const int ncol0 = n0 + wn + (lane & 3) * 2;
#pragma unroll
    for (int mi = 0; mi < 4; mi++) {
#pragma unroll
        for (int ni = 0; ni < 4; ni++) {
            float* o0 = out + (size_t)(mrow + mi * 16) * DOUT + ncol0 + ni * 8;
            float* o1 = o0 + 8 * DOUT;
            float2 v0, v1;
            v0.x = acc[mi][ni][0] * sc[ni][0] + bq[ni][0];
            v0.y = acc[mi][ni][1] * sc[ni][1] + bq[ni][1];
            v1.x = acc[mi][ni][2] * sc[ni][0] + bq[ni][0];
            v1.y = acc[mi][ni][3] * sc[ni][1] + bq[ni][1];
            *reinterpret_cast<float2*>(o0) = v0;
            *reinterpret_cast<float2*>(o1) = v1;
        }
    }
}

// ---------- launch ----------
extern "C" void kernel_launch(void* const* d_in, const int* in_sizes, int n_in,
                              void* d_out, int out_size) {
    const float* x  = (const float*)d_in[0];
    const float* w  = (const float*)d_in[1];
    const float* bi = (const float*)d_in[2];
    const float* ws = (const float*)d_in[3];
    const float* is = (const float*)d_in[4];
    float* out = (float*)d_out;

    cudaFuncSetAttribute(gemm_kernel,
                         cudaFuncAttributeMaxDynamicSharedMemorySize, SMEM_TOTAL);

    quant_kernel<<<NXB + NWB, 256>>>(x, w, ws, is);
    gemm_kernel<<<dim3(DOUT / BN, MROWS / BM), 256, SMEM_TOTAL>>>(bi, ws, is, out);
}

// round 14
// speedup vs baseline: 1.0234x; 1.0234x over previous
#include <cuda_runtime.h>
#include <cuda_bf16.h>
#include <cstdint>

// Problem dims
static constexpr int MROWS = 8192;   // B*S
static constexpr int DIN   = 4096;
static constexpr int DOUT  = 4096;

// GEMM tiling (2 CTAs/SM)
static constexpr int BM = 128, BN = 128, BK = 64;
static constexpr int KTILES = DIN / BK;          // 64
static constexpr int TILE_BYTES  = BM * BK * 2;  // 16384 per operand
static constexpr int STAGE_BYTES = 2 * TILE_BYTES;
static constexpr int SMEM_TOTAL  = 3 * STAGE_BYTES;  // 98304

// Quantized operands (device globals: no cudaMalloc allowed)
__device__ __nv_bfloat16 g_xq[(size_t)MROWS * DIN];  // 64 MB
__device__ __nv_bfloat16 g_wq[(size_t)DOUT * DIN];   // 32 MB

// ---------- helpers (base-sm_103-safe PTX only) ----------
__device__ __forceinline__ uint32_t smem_u32(const void* p) {
    uint32_t a;
    asm("{ .reg .u64 t; cvta.to.shared.u64 t, %1; cvt.u32.u64 %0, t; }"
        : "=r"(a) : "l"(p));
    return a;
}
__device__ __forceinline__ uint32_t swz(uint32_t o) { return o ^ ((o >> 3) & 0x70); }

__device__ __forceinline__ void cpasync16(uint32_t s, const void* g) {
    asm volatile("cp.async.cg.shared.global [%0], [%1], 16;" :: "r"(s), "l"(g));
}
__device__ __forceinline__ void cp_commit() {
    asm volatile("cp.async.commit_group;" ::: "memory");
}
__device__ __forceinline__ void cp_wait1() {
    asm volatile("cp.async.wait_group 1;" ::: "memory");
}
__device__ __forceinline__ void ldmx4(uint32_t* r, uint32_t addr) {
    asm volatile("ldmatrix.sync.aligned.m8n8.x4.shared.b16 {%0,%1,%2,%3}, [%4];"
                 : "=r"(r[0]), "=r"(r[1]), "=r"(r[2]), "=r"(r[3]) : "r"(addr));
}
__device__ __forceinline__ void mma16816(float* d, const uint32_t* a, const uint32_t* b) {
    asm volatile(
        "mma.sync.aligned.m16n8k16.row.col.f32.bf16.bf16.f32 "
        "{%0,%1,%2,%3}, {%4,%5,%6,%7}, {%8,%9}, {%0,%1,%2,%3};"
        : "+f"(d[0]), "+f"(d[1]), "+f"(d[2]), "+f"(d[3])
        : "r"(a[0]), "r"(a[1]), "r"(a[2]), "r"(a[3]), "r"(b[0]), "r"(b[1]));
}

// ---------- fused quantization (block-level dispatch, 8 elems/thread) ----------
static constexpr size_t NX = (size_t)MROWS * DIN;   // 33.55M
static constexpr size_t NW = (size_t)DOUT * DIN;    // 16.78M
static constexpr int ELEMS_PER_BLK = 256 * 8;       // 2048
static constexpr unsigned NXB = (unsigned)(NX / ELEMS_PER_BLK);  // 16384
static constexpr unsigned NWB = (unsigned)(NW / ELEMS_PER_BLK);  // 8192

__global__ void __launch_bounds__(256) quant_kernel(
    const float* __restrict__ x, const float* __restrict__ w,
    const float* __restrict__ wscale, const float* __restrict__ iscale) {
    const unsigned b = blockIdx.x;
    if (b < NXB) {
        const size_t i = (size_t)b * ELEMS_PER_BLK + (size_t)threadIdx.x * 8;
        const float is = iscale[0];
        float4 v0 = *reinterpret_cast<const float4*>(x + i);
        float4 v1 = *reinterpret_cast<const float4*>(x + i + 4);
        __nv_bfloat162 p0 = __floats2bfloat162_rn(truncf(v0.x * is), truncf(v0.y * is));
        __nv_bfloat162 p1 = __floats2bfloat162_rn(truncf(v0.z * is), truncf(v0.w * is));
        __nv_bfloat162 p2 = __floats2bfloat162_rn(truncf(v1.x * is), truncf(v1.y * is));
        __nv_bfloat162 p3 = __floats2bfloat162_rn(truncf(v1.z * is), truncf(v1.w * is));
        uint4 u;
        u.x = *reinterpret_cast<uint32_t*>(&p0);
        u.y = *reinterpret_cast<uint32_t*>(&p1);
        u.z = *reinterpret_cast<uint32_t*>(&p2);
        u.w = *reinterpret_cast<uint32_t*>(&p3);
        *reinterpret_cast<uint4*>(g_xq + i) = u;
    } else {
        const size_t i = (size_t)(b - NXB) * ELEMS_PER_BLK + (size_t)threadIdx.x * 8;
        const int row = (int)(i >> 12);  // / DIN (8 elems never cross a row)
        const float ws = wscale[row];
        float4 v0 = *reinterpret_cast<const float4*>(w + i);
        float4 v1 = *reinterpret_cast<const float4*>(w + i + 4);
        float f0 = (float)(int8_t)__float2int_rn(v0.x * ws);
        float f1 = (float)(int8_t)__float2int_rn(v0.y * ws);
        float f2 = (float)(int8_t)__float2int_rn(v0.z * ws);
        float f3 = (float)(int8_t)__float2int_rn(v0.w * ws);
        float f4 = (float)(int8_t)__float2int_rn(v1.x * ws);
        float f5 = (float)(int8_t)__float2int_rn(v1.y * ws);
        float f6 = (float)(int8_t)__float2int_rn(v1.z * ws);
        float f7 = (float)(int8_t)__float2int_rn(v1.w * ws);
        __nv_bfloat162 p0 = __floats2bfloat162_rn(f0, f1);
        __nv_bfloat162 p1 = __floats2bfloat162_rn(f2, f3);
        __nv_bfloat162 p2 = __floats2bfloat162_rn(f4, f5);
        __nv_bfloat162 p3 = __floats2bfloat162_rn(f6, f7);
        uint4 u;
        u.x = *reinterpret_cast<uint32_t*>(&p0);
        u.y = *reinterpret_cast<uint32_t*>(&p1);
        u.z = *reinterpret_cast<uint32_t*>(&p2);
        u.w = *reinterpret_cast<uint32_t*>(&p3);
        *reinterpret_cast<uint4*>(g_wq + i) = u;
    }
    // PDL: allow the dependent gemm grid to begin launching; it still waits
    // (griddepcontrol.wait) for this grid's full completion before loading.
    asm volatile("griddepcontrol.launch_dependents;" ::: "memory");
}

// ---------- GEMM: out = (Xq @ Wq^T) * sc + bias * sc ----------
// Exact R12 winner (best: 589.9us). Only addition: griddepcontrol.wait before
// the first global load, enabling PDL overlap with the quant kernel's tail.
__global__ void __launch_bounds__(256, 2) gemm_kernel(
    const float* __restrict__ bias, const float* __restrict__ wscale,
    const float* __restrict__ iscale, float* __restrict__ out) {
    extern __shared__ char smem[];
    const uint32_t sbase = smem_u32(smem);
    const int tid  = threadIdx.x;
    const int lane = tid & 31;
    const int warp = tid >> 5;
    const int wm = (warp >> 2) * 64;
    const int wn = (warp & 3) * 32;
    const int m0 = blockIdx.y * BM;
    const int n0 = blockIdx.x * BN;

    const int lrow0 = tid >> 3;
    const int lcol  = (tid & 7) * 8;
    const __nv_bfloat16* abase = g_xq + (size_t)(m0 + lrow0) * DIN + lcol;
    const __nv_bfloat16* bbase = g_wq + (size_t)(n0 + lrow0) * DIN + lcol;
    uint32_t soff[4];
#pragma unroll
    for (int u = 0; u < 4; u++)
        soff[u] = swz((uint32_t)((lrow0 + u * 32) * 128 + lcol * 2));

    auto load_tile = [&](int kt, uint32_t sA) {
        const uint32_t sB = sA + TILE_BYTES;
        const __nv_bfloat16* a0 = abase + (size_t)kt * BK;
        const __nv_bfloat16* b0 = bbase + (size_t)kt * BK;
#pragma unroll
        for (int u = 0; u < 4; u++) {
            cpasync16(sA + soff[u], a0 + (size_t)u * 32 * DIN);
            cpasync16(sB + soff[u], b0 + (size_t)u * 32 * DIN);
        }
    };

    float acc[4][4][4];
#pragma unroll
    for (int a = 0; a < 4; a++)
#pragma unroll
        for (int b = 0; b < 4; b++)
#pragma unroll
            for (int c = 0; c < 4; c++) acc[a][b][c] = 0.f;

    const int g = lane >> 3, r = lane & 7;
    uint32_t arow[4], brow[2];
#pragma unroll
    for (int mi = 0; mi < 4; mi++)
        arow[mi] = (uint32_t)((wm + mi * 16 + r + ((g & 1) ? 8 : 0)) * 128 +
                              (((g & 2) ? 8 : 0) * 2));
#pragma unroll
    for (int nb = 0; nb < 2; nb++)
        brow[nb] = (uint32_t)((wn + nb * 16 + r + ((g & 2) ? 8 : 0)) * 128 +
                              (((g & 1) ? 8 : 0) * 2));

    uint32_t bf[2][4][2];
    uint32_t af[2][4];

    auto loadB = [&](uint32_t sB, uint32_t kbo, uint32_t (*dst)[2]) {
#pragma unroll
        for (int nb = 0; nb < 2; nb++) {
            uint32_t t[4];
            ldmx4(t, sB + swz(brow[nb] + kbo));
            dst[nb * 2 + 0][0] = t[0]; dst[nb * 2 + 0][1] = t[1];
            dst[nb * 2 + 1][0] = t[2]; dst[nb * 2 + 1][1] = t[3];
        }
    };

    // PDL: block here until the quant grid has fully completed (no-op if the
    // kernel was launched without the PDL attribute).
    asm volatile("griddepcontrol.wait;" ::: "memory");

    // prologue: stages 0,1 in flight; tile0 resident; frags(kt0,ks0) loaded
    load_tile(0, sbase); cp_commit();
    load_tile(1, sbase + STAGE_BYTES); cp_commit();
    cp_wait1();
    __syncthreads();
    loadB(sbase + TILE_BYTES, 0, bf[0]);
    ldmx4(af[0], sbase + swz(arow[0]));

    const uint32_t slast = sbase + 2 * STAGE_BYTES;
    uint32_t cs = sbase;
    uint32_t ls = slast;

    for (int kt = 0; kt < KTILES; kt++) {
        if (kt + 2 < KTILES) load_tile(kt + 2, ls);
        cp_commit();

        const uint32_t sA = cs, sB = cs + TILE_BYTES;
        const uint32_t ns = (cs == slast) ? sbase : cs + STAGE_BYTES;
#pragma unroll
        for (int ks = 0; ks < 4; ks++) {
            if (ks == 3) cp_wait1();  // drain overlaps final ks block's MMAs
            const uint32_t kbo = (uint32_t)(ks * 32);
            const int cur = ks & 1;
#pragma unroll
            for (int mi = 0; mi < 4; mi++) {
                if (mi < 3) {
                    ldmx4(af[(mi + 1) & 1], sA + swz(arow[mi + 1] + kbo));
                } else if (ks < 3) {
                    loadB(sB, kbo + 32, bf[cur ^ 1]);
                    ldmx4(af[0], sA + swz(arow[0] + kbo + 32));
                }
#pragma unroll
                for (int ni = 0; ni < 4; ni++)
                    mma16816(acc[mi][ni], af[mi & 1], bf[cur][ni]);
            }
        }
        __syncthreads();
        if (kt + 1 < KTILES) {
            loadB(ns + TILE_BYTES, 0, bf[0]);
            ldmx4(af[0], ns + swz(arow[0]));
        }
        ls = cs;
        cs = ns;
    }

    // epilogue
    const float is = iscale[0];
    float sc[4][2], bq[4][2];
#pragma unroll
    for (int ni = 0; ni < 4; ni++)
#pragma unroll
        for (int j = 0; j < 2; j++) {
            const int n = n0 + wn + ni * 8 + (lane & 3) * 2 + j;
            const float s = 1.0f / (wscale[n] * is);
            sc[ni][j] = s;
            bq[ni][j] = bias[n] * s;
        }
    const int mrow = m0 + wm + (lane >> 2);
    const int ncol0 = n0 + wn + (lane & 3) * 2;
#pragma unroll
    for (int mi = 0; mi < 4; mi++) {
#pragma unroll
        for (int ni = 0; ni < 4; ni++) {
            float* o0 = out + (size_t)(mrow + mi * 16) * DOUT + ncol0 + ni * 8;
            float* o1 = o0 + 8 * DOUT;
            float2 v0, v1;
            v0.x = acc[mi][ni][0] * sc[ni][0] + bq[ni][0];
            v0.y = acc[mi][ni][1] * sc[ni][1] + bq[ni][1];
            v1.x = acc[mi][ni][2] * sc[ni][0] + bq[ni][0];
            v1.y = acc[mi][ni][3] * sc[ni][1] + bq[ni][1];
            *reinterpret_cast<float2*>(o0) = v0;
            *reinterpret_cast<float2*>(o1) = v1;
        }
    }
}

// ---------- launch ----------
extern "C" void kernel_launch(void* const* d_in, const int* in_sizes, int n_in,
                              void* d_out, int out_size) {
    const float* x  = (const float*)d_in[0];
    const float* w  = (const float*)d_in[1];
    const float* bi = (const float*)d_in[2];
    const float* ws = (const float*)d_in[3];
    const float* is = (const float*)d_in[4];
    float* out = (float*)d_out;

    cudaFuncSetAttribute(gemm_kernel,
                         cudaFuncAttributeMaxDynamicSharedMemorySize, SMEM_TOTAL);

    quant_kernel<<<NXB + NWB, 256>>>(x, w, ws, is);

    // PDL launch of the GEMM: overlaps its launch/prologue with quant's tail.
    cudaLaunchConfig_t cfg = {};
    cfg.gridDim = dim3(DOUT / BN, MROWS / BM);
    cfg.blockDim = dim3(256);
    cfg.dynamicSmemBytes = SMEM_TOTAL;
    cfg.stream = 0;
    cudaLaunchAttribute attr[1];
    attr[0].id = cudaLaunchAttributeProgrammaticStreamSerialization;
    attr[0].val.programmaticStreamSerializationAllowed = 1;
    cfg.attrs = attr;
    cfg.numAttrs = 1;
    cudaError_t err = cudaLaunchKernelEx(&cfg, gemm_kernel, bi, ws, is, out);
    if (err != cudaSuccess) {
        // Fallback: plain launch (griddepcontrol.wait degrades to no-op).
        gemm_kernel<<<dim3(DOUT / BN, MROWS / BM), 256, SMEM_TOTAL>>>(bi, ws, is, out);
    }
}